// round 14
// baseline (speedup 1.0000x reference)
#include <cuda_runtime.h>
#include <cooperative_groups.h>
#include <cstdint>
namespace cg = cooperative_groups;

// Problem constants (fixed by the reference)
#define Bn 32
#define Nn 1024
#define Fn 128
#define Dn 128
#define CS 8                        // cluster size = CTAs per batch
#define RPC 128                     // rows per CTA
#define SCALE 0.08838834764831843f  // 128^-0.5
#define NCH 8                       // TMA chunks per block
#define CH_BYTES (RPC / NCH * Fn * 4)   // 8192 bytes (16 rows)

__device__ __forceinline__ uint32_t smem_u32(const void* p) {
    return (uint32_t)__cvta_generic_to_shared(p);
}

__global__ __launch_bounds__(256, 2) __cluster_dims__(CS, 1, 1)
void ga(const float* __restrict__ X, const float* __restrict__ mask,
        const float* __restrict__ Wq, const float* __restrict__ bq,
        const float* __restrict__ Wk, const float* __restrict__ bk,
        const float* __restrict__ Wv, const float* __restrict__ bv,
        float* __restrict__ attn, float* __restrict__ ctx) {
    extern __shared__ float dyn[];
    float* Xt  = dyn;                 // [128][128]  X tile (rows rowC..rowC+127)
    float* sWk = dyn + Fn * Fn;       // [128][17]   Wk[:, dBase..dBase+16)
    float* sWq = sWk + Fn * 17;       // [128][17]   Wq[d][dBase..dBase+16)
    float* sWv = sWq + Fn * 17;       // [128][17]   Wv[:, dBase..dBase+16)

    __shared__ __align__(16) float shXs[Fn];    // this block's colsum partial
    __shared__ float shXsF[Fn];                 // full Xsum (gathered)
    __shared__ float shKsl[16];                 // ksum slice
    __shared__ float shUp[Fn];                  // u partial
    __shared__ float shUF[Fn];                  // full u
    __shared__ float shAgg[RPC];
    __shared__ __align__(16) float shAcc[Fn];
    __shared__ float shY[Fn];
    __shared__ float shMask[RPC];
    __shared__ float shBk[16], shBq[16], shBv[16];
    __shared__ float prt[16][16];
    __shared__ float prt2[2][Fn];
    __shared__ float4 shP[8][32];
    __shared__ float shMw[8], shSw[8];
    __shared__ float shMS[2];
    __shared__ float Mall[CS], Sall[CS];
    __shared__ float cLoc, cFull;
    __shared__ __align__(8) unsigned long long mbar[NCH];

    cg::cluster_group cluster = cg::this_cluster();
    int t = threadIdx.x, w = t >> 5, lane = t & 31;
    int bid = blockIdx.x, b = bid >> 3, rank = bid & 7;
    int rowC = rank * RPC;
    int dBase = rank * 16;

    uint32_t mb0 = smem_u32(&mbar[0]);
    uint32_t xt = smem_u32(Xt);

    // ---- prologue: mbarriers + 8 chunked bulk copies; weight staging --------
    if (t < NCH)
        asm volatile("mbarrier.init.shared.b64 [%0], 1;"
                     :: "r"(mb0 + t * 8) : "memory");
    __syncthreads();
    if (t == 0) {
        const float* src0 = X + ((size_t)b * Nn + rowC) * Fn;
        #pragma unroll
        for (int ch = 0; ch < NCH; ch++) {
            uint32_t mbc = mb0 + ch * 8;
            asm volatile("mbarrier.arrive.expect_tx.shared.b64 _, [%0], %1;"
                         :: "r"(mbc), "r"((uint32_t)CH_BYTES) : "memory");
            asm volatile(
                "cp.async.bulk.shared::cluster.global.mbarrier::complete_tx::bytes "
                "[%0], [%1], %2, [%3];"
                :: "r"(xt + ch * CH_BYTES),
                   "l"(src0 + (size_t)ch * (CH_BYTES / 4)),
                   "r"((uint32_t)CH_BYTES), "r"(mbc) : "memory");
        }
    }

    // weight slices (independent of X): 128 rows x 16 cols each, stride 17
    {
        int f = t >> 1, hh = (t & 1) * 8;
        float4 v0 = *(const float4*)(Wk + (size_t)f * Dn + dBase + hh);
        float4 v1 = *(const float4*)(Wk + (size_t)f * Dn + dBase + hh + 4);
        float* p = sWk + f * 17 + hh;
        p[0]=v0.x; p[1]=v0.y; p[2]=v0.z; p[3]=v0.w;
        p[4]=v1.x; p[5]=v1.y; p[6]=v1.z; p[7]=v1.w;
        v0 = *(const float4*)(Wq + (size_t)f * Dn + dBase + hh);
        v1 = *(const float4*)(Wq + (size_t)f * Dn + dBase + hh + 4);
        p = sWq + f * 17 + hh;
        p[0]=v0.x; p[1]=v0.y; p[2]=v0.z; p[3]=v0.w;
        p[4]=v1.x; p[5]=v1.y; p[6]=v1.z; p[7]=v1.w;
        v0 = *(const float4*)(Wv + (size_t)f * Dn + dBase + hh);
        v1 = *(const float4*)(Wv + (size_t)f * Dn + dBase + hh + 4);
        p = sWv + f * 17 + hh;
        p[0]=v0.x; p[1]=v0.y; p[2]=v0.z; p[3]=v0.w;
        p[4]=v1.x; p[5]=v1.y; p[6]=v1.z; p[7]=v1.w;
    }
    if (t < 128) shMask[t] = mask[b * Nn + rowC + t];
    if (t < 16) { shBk[t] = bk[dBase + t]; shBq[t] = bq[dBase + t]; shBv[t] = bv[dBase + t]; }
    __syncthreads();

    // ---- Phase A: per-warp chunk wait, then column-sum of its 16 rows -------
    {
        uint32_t mbc = mb0 + w * 8;
        unsigned done = 0;
        while (!done) {
            asm volatile(
                "{\n\t.reg .pred p;\n\t"
                "mbarrier.try_wait.parity.shared.b64 p, [%1], %2;\n\t"
                "selp.b32 %0, 1, 0, p;\n\t}"
                : "=r"(done) : "r"(mbc), "r"(0u) : "memory");
        }
        const float4* X4 = (const float4*)Xt;
        int r0 = w * 16;
        float4 cs = X4[(size_t)r0 * 32 + lane];
        #pragma unroll
        for (int r = 1; r < 16; r++) {
            float4 xx = X4[(size_t)(r0 + r) * 32 + lane];
            cs.x += xx.x; cs.y += xx.y; cs.z += xx.z; cs.w += xx.w;
        }
        shP[w][lane] = cs;
    }
    __syncthreads();     // also guarantees ALL chunks arrived (each warp waited its own)
    if (t < 32) {
        float4 sum = shP[0][t];
        #pragma unroll
        for (int g = 1; g < 8; g++) {
            float4 p = shP[g][t];
            sum.x += p.x; sum.y += p.y; sum.z += p.z; sum.w += p.w;
        }
        ((float4*)shXs)[t] = sum;
    }
    __syncthreads();
    cluster.sync();                                           // #1

    // ---- Phase B1: gather Xsum; ksum slice; c_local; u partial --------------
    if (t < 128) {
        float s = 0.f;
        #pragma unroll
        for (int r = 0; r < CS; r++) {
            const float* p = (const float*)cluster.map_shared_rank(shXs, r);
            s += p[t];
        }
        shXsF[t] = s;
    }
    __syncthreads();
    {
        int d = t & 15, seg = t >> 4;
        float a = 0.f;
        #pragma unroll
        for (int j = 0; j < 8; j++) {
            int f = seg * 8 + j;
            a += shXsF[f] * sWk[f * 17 + d];
        }
        prt[seg][d] = a;
    }
    __syncthreads();
    if (t < 16) {
        float a = 0.f;
        #pragma unroll
        for (int s = 0; s < 16; s++) a += prt[s][t];
        shKsl[t] = a + (float)Nn * shBk[t];
    }
    __syncthreads();
    {
        float v = (t < 16) ? shBq[t] * shKsl[t] : 0.f;
        if (w == 0) {
            #pragma unroll
            for (int off = 8; off > 0; off >>= 1)
                v += __shfl_xor_sync(0xffffffffu, v, off);
            if (lane == 0) cLoc = v;
        }
    }
    {
        int d = t & 127, h = t >> 7;
        float a = 0.f;
        #pragma unroll
        for (int j = 0; j < 8; j++) {
            int i = h * 8 + j;
            a += sWq[d * 17 + i] * shKsl[i];
        }
        prt2[h][d] = a;
    }
    __syncthreads();
    if (t < 128) shUp[t] = prt2[0][t] + prt2[1][t];
    __syncthreads();
    cluster.sync();                                           // #2

    // ---- Phase B2: gather full u and c --------------------------------------
    if (t < 128) {
        float s = 0.f;
        #pragma unroll
        for (int r = 0; r < CS; r++) {
            const float* p = (const float*)cluster.map_shared_rank(shUp, r);
            s += p[t];
        }
        shUF[t] = s;
    }
    {
        float cv = 0.f;
        if (w == 0 && lane < CS)
            cv = *(const float*)cluster.map_shared_rank(&cLoc, lane);
        if (w == 0) {
            #pragma unroll
            for (int off = 4; off > 0; off >>= 1)
                cv += __shfl_xor_sync(0xffffffffu, cv, off);
            if (lane == 0) cFull = cv;
        }
    }
    __syncthreads();

    // ---- Phase C: agg + softmax partials from smem X ------------------------
    {
        float c = cFull;
        float4 uv = ((const float4*)shUF)[lane];
        const float4* X4 = (const float4*)Xt;
        int rw = w * 16;

        float Mw = -3.0e38f, Sw = 0.f;
        float4 accw = make_float4(0.f, 0.f, 0.f, 0.f);
        #pragma unroll
        for (int g = 0; g < 2; g++) {
            float4 x[8];
            float d[8];
            #pragma unroll
            for (int r = 0; r < 8; r++) {
                x[r] = X4[(size_t)(rw + g * 8 + r) * 32 + lane];
                d[r] = x[r].x * uv.x + x[r].y * uv.y + x[r].z * uv.z + x[r].w * uv.w;
            }
            #pragma unroll
            for (int off = 16; off > 0; off >>= 1) {
                #pragma unroll
                for (int r = 0; r < 8; r++)
                    d[r] += __shfl_xor_sync(0xffffffffu, d[r], off);
            }
            float a[8];
            #pragma unroll
            for (int r = 0; r < 8; r++)
                a[r] = (shMask[rw + g * 8 + r] != 0.f) ? SCALE * (d[r] + c) : -1e9f;

            float myA = a[0];
            #pragma unroll
            for (int r = 1; r < 8; r++) if (lane == r) myA = a[r];
            if (lane < 8) shAgg[rw + g * 8 + lane] = myA;

            float M8 = a[0];
            #pragma unroll
            for (int r = 1; r < 8; r++) M8 = fmaxf(M8, a[r]);
            float ev[8], S8 = 0.f;
            #pragma unroll
            for (int r = 0; r < 8; r++) { ev[r] = __expf(a[r] - M8); S8 += ev[r]; }
            float4 a8 = make_float4(0.f, 0.f, 0.f, 0.f);
            #pragma unroll
            for (int r = 0; r < 8; r++) {
                a8.x += ev[r] * x[r].x; a8.y += ev[r] * x[r].y;
                a8.z += ev[r] * x[r].z; a8.w += ev[r] * x[r].w;
            }
            float nM = fmaxf(Mw, M8);
            float s0 = __expf(Mw - nM), s1 = __expf(M8 - nM);
            Sw = Sw * s0 + S8 * s1;
            accw.x = accw.x * s0 + a8.x * s1;
            accw.y = accw.y * s0 + a8.y * s1;
            accw.z = accw.z * s0 + a8.z * s1;
            accw.w = accw.w * s0 + a8.w * s1;
            Mw = nM;
        }
        if (lane == 0) { shMw[w] = Mw; shSw[w] = Sw; }
        shP[w][lane] = accw;
    }
    __syncthreads();
    if (t < 32) {
        float bMb = shMw[0];
        #pragma unroll
        for (int j = 1; j < 8; j++) bMb = fmaxf(bMb, shMw[j]);
        float Sb = 0.f;
        float4 ya = make_float4(0.f, 0.f, 0.f, 0.f);
        #pragma unroll
        for (int j = 0; j < 8; j++) {
            float f = __expf(shMw[j] - bMb);
            Sb += f * shSw[j];
            float4 p = shP[j][t];
            ya.x += f * p.x; ya.y += f * p.y; ya.z += f * p.z; ya.w += f * p.w;
        }
        ((float4*)shAcc)[t] = ya;
        if (t == 0) { shMS[0] = bMb; shMS[1] = Sb; }
    }
    __syncthreads();
    cluster.sync();                                           // #3

    // ---- Phase D: cluster merge, attn, y gather, ctx (all before final sync)
    if (t < CS) {
        const float* pMS = (const float*)cluster.map_shared_rank(shMS, t);
        Mall[t] = pMS[0];
        Sall[t] = pMS[1];
    }
    __syncthreads();
    float bM = Mall[0];
    #pragma unroll
    for (int j = 1; j < CS; j++) bM = fmaxf(bM, Mall[j]);
    float Z = 0.f;
    #pragma unroll
    for (int j = 0; j < CS; j++) Z += __expf(Mall[j] - bM) * Sall[j];
    float invZ = 1.0f / Z;

    if (t < 128)
        attn[b * Nn + rowC + t] = __expf(shAgg[t] - bM) * invZ;

    if (t < 128) {
        float y = 0.f;
        #pragma unroll
        for (int r = 0; r < CS; r++) {
            const float* pa = (const float*)cluster.map_shared_rank(shAcc, r);
            y += __expf(Mall[r] - bM) * pa[t];
        }
        shY[t] = y * invZ;
    }
    __syncthreads();

    // ctx slice: 16 outputs per block, local data only (off the sync path)
    {
        int d = t & 15, seg = t >> 4;
        float a = 0.f;
        #pragma unroll
        for (int j = 0; j < 8; j++) {
            int f = seg * 8 + j;
            a += shY[f] * sWv[f * 17 + d];
        }
        prt[seg][d] = a;
    }
    __syncthreads();
    if (t < 16) {
        float a = 0.f;
        #pragma unroll
        for (int s = 0; s < 16; s++) a += prt[s][t];
        ctx[b * Dn + dBase + t] = shBv[t] + a;
    }

    cluster.sync();      // trailing: keep smem alive for peers' earlier gathers
}

// ---------------------------------------------------------------------------
extern "C" void kernel_launch(void* const* d_in, const int* in_sizes, int n_in,
                              void* d_out, int out_size) {
    const float* X    = (const float*)d_in[0];
    const float* mask = (const float*)d_in[1];
    const float* Wq   = (const float*)d_in[2];
    const float* bq   = (const float*)d_in[3];
    const float* Wk   = (const float*)d_in[4];
    const float* bk   = (const float*)d_in[5];
    const float* Wv   = (const float*)d_in[6];
    const float* bv   = (const float*)d_in[7];
    float* out  = (float*)d_out;
    float* attn = out;              // [B,N,1]
    float* ctx  = out + Bn * Nn;    // [B,D]

    const int smemBytes = (Fn * Fn + 3 * Fn * 17) * (int)sizeof(float); // 91648
    static bool attrSet = false;
    if (!attrSet) {
        cudaFuncSetAttribute(ga, cudaFuncAttributeMaxDynamicSharedMemorySize, smemBytes);
        attrSet = true;
    }

    ga<<<Bn * CS, 256, smemBytes>>>(X, mask, Wq, bq, Wk, bk, Wv, bv, attn, ctx);
}